// round 6
// baseline (speedup 1.0000x reference)
#include <cuda_runtime.h>
#include <cstdint>

#define NMAX 1000000
#define EMAX 1000000
#define HDIM 64
#define FIN  19
#define LN_EPS 1e-5f

// ---------------- device scratch ----------------
__device__ float g_h[(size_t)NMAX * HDIM];
__device__ float g_hpA[(size_t)NMAX * HDIM];   // compact parent rows, buffer A
__device__ float g_hpB[(size_t)NMAX * HDIM];   // compact parent rows, buffer B
__device__ int   g_cnt[NMAX];
__device__ int   g_row[NMAX];
__device__ int   g_pos[NMAX];
__device__ int   g_rank[NMAX];                 // node -> plist position, -1 if no children
__device__ int   g_children[EMAX];
__device__ int   g_crank[EMAX];                // rank of each child (precomputed)
__device__ int   g_plist[NMAX];
__device__ int   g_nplist;
__device__ int   g_bsum[1024];
__device__ int   g_boff[1024];
__device__ int   g_is64;
__device__ float g_scores[4096];

__device__ __forceinline__ float leaky(float v) { return v > 0.f ? v : 0.01f * v; }

__device__ __forceinline__ float wsum(float v) {
#pragma unroll
    for (int o = 16; o; o >>= 1) v += __shfl_xor_sync(0xffffffffu, v, o);
    return v;
}

// ---------------- packed f32x2 helpers ----------------
__device__ __forceinline__ unsigned long long pack2(float lo, float hi) {
    unsigned long long d;
    asm("mov.b64 %0, {%1, %2};" : "=l"(d) : "r"(__float_as_uint(lo)), "r"(__float_as_uint(hi)));
    return d;
}
__device__ __forceinline__ unsigned long long dup2(float v) {
    unsigned long long d;
    unsigned u = __float_as_uint(v);
    asm("mov.b64 %0, {%1, %1};" : "=l"(d) : "r"(u));
    return d;
}
__device__ __forceinline__ void unpack2(unsigned long long v, float& lo, float& hi) {
    unsigned a, b;
    asm("mov.b64 {%0, %1}, %2;" : "=r"(a), "=r"(b) : "l"(v));
    lo = __uint_as_float(a); hi = __uint_as_float(b);
}
__device__ __forceinline__ void fma2(unsigned long long& a, unsigned long long b, unsigned long long c) {
    asm("fma.rn.f32x2 %0, %1, %2, %0;" : "+l"(a) : "l"(b), "l"(c));
}
__device__ __forceinline__ void add2(unsigned long long& a, unsigned long long b) {
    asm("add.rn.f32x2 %0, %0, %1;" : "+l"(a) : "l"(b));
}
__device__ __forceinline__ void mul2(unsigned long long& a, unsigned long long b) {
    asm("mul.rn.f32x2 %0, %0, %1;" : "+l"(a) : "l"(b));
}

__device__ __forceinline__ int idx_at(const void* p, int i, int is64, int n) {
    long long v = is64 ? ((const long long*)p)[i] : (long long)((const int*)p)[i];
    unsigned u = (unsigned)v;
    return (u < (unsigned)n) ? (int)u : 0;
}

// ---------------- dtype detection ----------------
__global__ void detect_kernel(const unsigned* __restrict__ words, int nPairs) {
    __shared__ int flag;
    if (threadIdx.x == 0) flag = 0;
    __syncthreads();
    int lim = nPairs < 256 ? nPairs : 256;
    int i = threadIdx.x;
    if (i < lim && words[2 * i + 1] != 0u) flag = 1;
    __syncthreads();
    if (threadIdx.x == 0) g_is64 = (flag == 0);
}

// ---------------- CSR build ----------------
__global__ void zero_kernel(int n) {
    int i = blockIdx.x * blockDim.x + threadIdx.x;
    if (i < n) { g_cnt[i] = 0; g_pos[i] = 0; g_rank[i] = -1; }
    if (i == 0) g_nplist = 0;
}

__global__ void hist_kernel(const void* __restrict__ ei, int E, int nN) {
    int is64 = g_is64;
    int e = blockIdx.x * blockDim.x + threadIdx.x;
    if (e < E) atomicAdd(&g_cnt[idx_at(ei, e, is64, nN)], 1);
}

__global__ void scan_cnt_kernel(int n) {
    __shared__ int s[256];
    int t = threadIdx.x;
    int base = blockIdx.x * 1024 + t * 4;
    int v0 = (base + 0 < n) ? g_cnt[base + 0] : 0;
    int v1 = (base + 1 < n) ? g_cnt[base + 1] : 0;
    int v2 = (base + 2 < n) ? g_cnt[base + 2] : 0;
    int v3 = (base + 3 < n) ? g_cnt[base + 3] : 0;
    int tsum = v0 + v1 + v2 + v3;
    s[t] = tsum; __syncthreads();
    for (int o = 1; o < 256; o <<= 1) {
        int add = (t >= o) ? s[t - o] : 0;
        __syncthreads();
        s[t] += add;
        __syncthreads();
    }
    int excl = s[t] - tsum;
    if (base + 0 < n) g_row[base + 0] = excl;
    if (base + 1 < n) g_row[base + 1] = excl + v0;
    if (base + 2 < n) g_row[base + 2] = excl + v0 + v1;
    if (base + 3 < n) g_row[base + 3] = excl + v0 + v1 + v2;
    if (t == 255) g_bsum[blockIdx.x] = s[255];
}

__global__ void scan_bsum_kernel(int n) {
    __shared__ int s[256];
    int t = threadIdx.x;
    int base = t * 4;
    int v0 = (base + 0 < n) ? g_bsum[base + 0] : 0;
    int v1 = (base + 1 < n) ? g_bsum[base + 1] : 0;
    int v2 = (base + 2 < n) ? g_bsum[base + 2] : 0;
    int v3 = (base + 3 < n) ? g_bsum[base + 3] : 0;
    int tsum = v0 + v1 + v2 + v3;
    s[t] = tsum; __syncthreads();
    for (int o = 1; o < 256; o <<= 1) {
        int add = (t >= o) ? s[t - o] : 0;
        __syncthreads();
        s[t] += add;
        __syncthreads();
    }
    int excl = s[t] - tsum;
    if (base + 0 < n) g_boff[base + 0] = excl;
    if (base + 1 < n) g_boff[base + 1] = excl + v0;
    if (base + 2 < n) g_boff[base + 2] = excl + v0 + v1;
    if (base + 3 < n) g_boff[base + 3] = excl + v0 + v1 + v2;
}

__global__ void addback_kernel(int n) {
    int i = blockIdx.x * blockDim.x + threadIdx.x;
    int c = (i < n) ? g_cnt[i] : 0;
    if (i < n) g_row[i] += g_boff[i >> 10];
    bool act = (c > 0);
    unsigned mask = __ballot_sync(0xffffffffu, act);
    if (act) {
        int lane = threadIdx.x & 31;
        int leader = __ffs(mask) - 1;
        int rank = __popc(mask & ((1u << lane) - 1u));
        int basep = 0;
        if (lane == leader) basep = atomicAdd(&g_nplist, __popc(mask));
        basep = __shfl_sync(mask, basep, leader);
        g_plist[basep + rank] = i;
        g_rank[i] = basep + rank;
    }
}

__global__ void scatter_kernel(const void* __restrict__ ei, int E, int nN) {
    int is64 = g_is64;
    int e = blockIdx.x * blockDim.x + threadIdx.x;
    if (e < E) {
        int p = idx_at(ei, e, is64, nN);
        int c = idx_at(ei, E + e, is64, nN);
        int pos = atomicAdd(&g_pos[p], 1);
        int slot = g_row[p] + pos;
        g_children[slot] = c;
        g_crank[slot] = g_rank[c];
    }
}

// ---------------- embedding (packed f32x2, 4 warps/block, 10 nodes/warp) ------
__global__ __launch_bounds__(128) void embed_kernel(
    const float* __restrict__ x, const float* __restrict__ pW, const float* __restrict__ pb,
    const float* __restrict__ eW, const float* __restrict__ eb,
    const float* __restrict__ gamma, const float* __restrict__ beta, int nN)
{
    __shared__ float4 s_pW[10 * 32];
    __shared__ float4 s_eW[2 * 32 * 32];
    __shared__ float4 s_x[4][10][5];
    __shared__ float4 s_h[4][10][16];
    int tid = threadIdx.x;
    for (int i = tid; i < 10 * 32; i += 128) {
        int kp = i >> 5, l = i & 31;
        int k0 = 2 * kp, k1 = 2 * kp + 1;
        float a = (k0 < FIN) ? pW[k0 * 64 + l]      : 0.f;
        float b = (k0 < FIN) ? pW[k0 * 64 + l + 32] : 0.f;
        float c = (k1 < FIN) ? pW[k1 * 64 + l]      : 0.f;
        float d = (k1 < FIN) ? pW[k1 * 64 + l + 32] : 0.f;
        s_pW[i] = make_float4(a, b, c, d);
    }
    for (int i = tid; i < 2 * 32 * 32; i += 128) {
        int li = i >> 10, r = i & 1023, kp = r >> 5, l = r & 31;
        const float* W = eW + li * 4096;
        int k0 = 2 * kp;
        s_eW[i] = make_float4(W[k0 * 64 + l], W[k0 * 64 + l + 32],
                              W[(k0 + 1) * 64 + l], W[(k0 + 1) * 64 + l + 32]);
    }
    __syncthreads();

    int wid = tid >> 5, lane = tid & 31;
    unsigned long long pb2 = pack2(pb[lane], pb[lane + 32]);
    unsigned long long eb2[2];
    float gl[2], ghi[2], bl[2], bh[2];
#pragma unroll
    for (int i2 = 0; i2 < 2; i2++) {
        eb2[i2] = pack2(eb[i2 * 64 + lane], eb[i2 * 64 + lane + 32]);
        gl[i2] = gamma[i2 * 64 + lane];  ghi[i2] = gamma[i2 * 64 + lane + 32];
        bl[i2] = beta[i2 * 64 + lane];   bh[i2] = beta[i2 * 64 + lane + 32];
    }
    float* sxf = (float*)&s_x[wid][0][0];
    float* shf = (float*)&s_h[wid][0][0];

    int nG = (nN + 9) / 10;
    for (int g = blockIdx.x * 4 + wid; g < nG; g += gridDim.x * 4) {
        int n0 = g * 10;
        int rem = nN - n0;
        size_t base = (size_t)n0 * FIN;
        size_t lim = (size_t)nN * FIN;
        __syncwarp();
        for (int idx = lane; idx < 10 * FIN; idx += 32) {
            float v = (base + idx < lim) ? x[base + idx] : 0.f;
            int r = idx / FIN, kk = idx - r * FIN;
            sxf[r * 20 + kk] = v;
        }
        if (lane < 10) sxf[lane * 20 + 19] = 0.f;
        __syncwarp();

        unsigned long long acc[10];
#pragma unroll
        for (int r = 0; r < 10; r++) acc[r] = pb2;
#pragma unroll
        for (int kq = 0; kq < 5; ++kq) {
            ulonglong2 w0 = *(const ulonglong2*)&s_pW[(2 * kq) * 32 + lane];
            ulonglong2 w1 = *(const ulonglong2*)&s_pW[(2 * kq + 1) * 32 + lane];
#pragma unroll
            for (int r = 0; r < 10; r++) {
                float4 xv = s_x[wid][r][kq];
                fma2(acc[r], w0.x, dup2(xv.x));
                fma2(acc[r], w0.y, dup2(xv.y));
                fma2(acc[r], w1.x, dup2(xv.z));
                fma2(acc[r], w1.y, dup2(xv.w));
            }
        }
        float hl[10], hh[10];
#pragma unroll
        for (int r = 0; r < 10; r++) {
            float a, b; unpack2(acc[r], a, b);
            hl[r] = leaky(a); hh[r] = leaky(b);
        }

#pragma unroll
        for (int li = 0; li < 2; ++li) {
#pragma unroll
            for (int r = 0; r < 10; r++) { shf[r * 64 + lane] = hl[r]; shf[r * 64 + lane + 32] = hh[r]; }
            __syncwarp();
#pragma unroll
            for (int r = 0; r < 10; r++) acc[r] = eb2[li];
#pragma unroll
            for (int kq = 0; kq < 16; ++kq) {
                ulonglong2 w0 = *(const ulonglong2*)&s_eW[li * 1024 + (2 * kq) * 32 + lane];
                ulonglong2 w1 = *(const ulonglong2*)&s_eW[li * 1024 + (2 * kq + 1) * 32 + lane];
#pragma unroll
                for (int r = 0; r < 10; r++) {
                    float4 hv = s_h[wid][r][kq];
                    fma2(acc[r], w0.x, dup2(hv.x));
                    fma2(acc[r], w0.y, dup2(hv.y));
                    fma2(acc[r], w1.x, dup2(hv.z));
                    fma2(acc[r], w1.y, dup2(hv.w));
                }
            }
#pragma unroll
            for (int r = 0; r < 10; r++) {
                float tl, th; unpack2(acc[r], tl, th);
                float ul = hl[r] + leaky(tl);
                float uh = hh[r] + leaky(th);
                float s1 = wsum(ul + uh);
                float s2 = wsum(ul * ul + uh * uh);
                float mu = s1 * (1.f / 64.f);
                float var = s2 * (1.f / 64.f) - mu * mu;
                float inv = rsqrtf(var + LN_EPS);
                hl[r] = (ul - mu) * inv * gl[li] + bl[li];
                hh[r] = (uh - mu) * inv * ghi[li] + bh[li];
            }
            __syncwarp();
        }
#pragma unroll
        for (int r = 0; r < 10; r++) {
            if (r < rem) {
                g_h[(size_t)(n0 + r) * 64 + lane] = hl[r];
                g_h[(size_t)(n0 + r) * 64 + lane + 32] = hh[r];
            }
        }
    }
}

// ------- fused message passing: gather-mean + MLP + residual, double-buffered ------
// inSel: 0 -> read everything from g_h (iteration 0); 1 -> parents from g_hpA; 2 -> g_hpB
// outSel: 1 -> write updated parent rows to g_hpA; 2 -> g_hpB
__global__ __launch_bounds__(256) void mp_kernel(
    const float* __restrict__ W1g, const float* __restrict__ b1g,
    const float* __restrict__ W2g, const float* __restrict__ b2g,
    int inSel, int outSel)
{
    __shared__ float4 s_W1[1024];
    __shared__ float4 s_W2[1024];
    __shared__ float4 s_hq[8][8][16];
    int tid = threadIdx.x;
    for (int i = tid; i < 1024; i += 256) {
        int kp = i >> 5, l = i & 31; int k0 = kp * 2;
        s_W1[i] = make_float4(W1g[k0 * 64 + l], W1g[k0 * 64 + l + 32],
                              W1g[(k0 + 1) * 64 + l], W1g[(k0 + 1) * 64 + l + 32]);
        s_W2[i] = make_float4(W2g[k0 * 64 + l], W2g[k0 * 64 + l + 32],
                              W2g[(k0 + 1) * 64 + l], W2g[(k0 + 1) * 64 + l + 32]);
    }
    __syncthreads();
    const float* bufIn = (inSel == 1) ? g_hpA : (inSel == 2) ? g_hpB : nullptr;
    float* bufOut = (outSel == 1) ? g_hpA : g_hpB;
    int wid = tid >> 5, lane = tid & 31;
    unsigned long long b12 = pack2(b1g[lane], b1g[lane + 32]);
    unsigned long long b22 = pack2(b2g[lane], b2g[lane + 32]);
    float* shf = (float*)&s_hq[wid][0][0];
    int np = g_nplist;
    int nG = (np + 7) >> 3;
    for (int g = blockIdx.x * 8 + wid; g < nG; g += gridDim.x * 8) {
        int i0 = g << 3;
        __syncwarp();
        int st[8], cc[8], pl[8];
        int maxc = 0;
#pragma unroll
        for (int r = 0; r < 8; r++) {
            if (i0 + r < np) {
                int p = g_plist[i0 + r];
                pl[r] = p;
                st[r] = g_row[p];
                cc[r] = g_cnt[p];
                maxc = max(maxc, cc[r]);
            } else { pl[r] = 0; st[r] = 0; cc[r] = 0; }
        }
        // own parent rows (residual) — issue early, independent loads
        float ownl[8], ownh[8];
#pragma unroll
        for (int r = 0; r < 8; r++) {
            if (i0 + r < np) {
                const float* own = bufIn ? bufIn + (size_t)(i0 + r) * 64
                                         : g_h + (size_t)pl[r] * 64;
                ownl[r] = own[lane];
                ownh[r] = own[lane + 32];
            } else { ownl[r] = 0.f; ownh[r] = 0.f; }
        }
        unsigned long long sum[8];
#pragma unroll
        for (int r = 0; r < 8; r++) sum[r] = 0ull;
        for (int t = 0; t < maxc; ++t) {
            unsigned long long hv[8];
#pragma unroll
            for (int r = 0; r < 8; r++) {
                if (t < cc[r]) {
                    int slot = st[r] + t;
                    int ch = g_children[slot];
                    int rk = g_crank[slot];
                    const float* src = (rk >= 0 && bufIn) ? bufIn + (size_t)rk * 64
                                                          : g_h + (size_t)ch * 64;
                    hv[r] = *(const unsigned long long*)(src + 2 * lane);
                }
            }
#pragma unroll
            for (int r = 0; r < 8; r++)
                if (t < cc[r]) add2(sum[r], hv[r]);
        }
#pragma unroll
        for (int r = 0; r < 8; r++)
            if (cc[r] > 0) mul2(sum[r], dup2(1.f / (float)cc[r]));
#pragma unroll
        for (int r = 0; r < 8; r++)
            *(unsigned long long*)(shf + r * 64 + 2 * lane) = sum[r];
        __syncwarp();

        unsigned long long acc[8];
#pragma unroll
        for (int r = 0; r < 8; r++) acc[r] = b12;
#pragma unroll
        for (int kq = 0; kq < 16; ++kq) {
            ulonglong2 w0 = *(const ulonglong2*)&s_W1[(2 * kq) * 32 + lane];
            ulonglong2 w1 = *(const ulonglong2*)&s_W1[(2 * kq + 1) * 32 + lane];
#pragma unroll
            for (int r = 0; r < 8; r++) {
                float4 hv = s_hq[wid][r][kq];
                fma2(acc[r], w0.x, dup2(hv.x));
                fma2(acc[r], w0.y, dup2(hv.y));
                fma2(acc[r], w1.x, dup2(hv.z));
                fma2(acc[r], w1.y, dup2(hv.w));
            }
        }
        __syncwarp();
#pragma unroll
        for (int r = 0; r < 8; r++) {
            float a, b; unpack2(acc[r], a, b);
            shf[r * 64 + lane] = leaky(a);
            shf[r * 64 + lane + 32] = leaky(b);
        }
        __syncwarp();
#pragma unroll
        for (int r = 0; r < 8; r++) acc[r] = b22;
#pragma unroll
        for (int kq = 0; kq < 16; ++kq) {
            ulonglong2 w0 = *(const ulonglong2*)&s_W2[(2 * kq) * 32 + lane];
            ulonglong2 w1 = *(const ulonglong2*)&s_W2[(2 * kq + 1) * 32 + lane];
#pragma unroll
            for (int r = 0; r < 8; r++) {
                float4 hv = s_hq[wid][r][kq];
                fma2(acc[r], w0.x, dup2(hv.x));
                fma2(acc[r], w0.y, dup2(hv.y));
                fma2(acc[r], w1.x, dup2(hv.z));
                fma2(acc[r], w1.y, dup2(hv.w));
            }
        }
#pragma unroll
        for (int r = 0; r < 8; r++) {
            if (i0 + r < np) {
                float a, b; unpack2(acc[r], a, b);
                float* o = bufOut + (size_t)(i0 + r) * 64;
                o[lane]      = ownl[r] + a;
                o[lane + 32] = ownh[r] + b;
            }
        }
    }
}

// ---------------- score head (parallel) + softmax ----------------
__global__ __launch_bounds__(256) void scores_kernel(
    const void* __restrict__ cand,
    const float* __restrict__ W1g, const float* __restrict__ b1g,
    const float* __restrict__ W2g, const float* __restrict__ b2g,
    int K, int nN)
{
    __shared__ float4 s_W1[1024];
    __shared__ float4 s_hq[8][4][16];
    int tid = threadIdx.x;
    int is64 = g_is64;
    for (int i = tid; i < 1024; i += 256) {
        int kp = i >> 5, l = i & 31; int k0 = kp * 2;
        s_W1[i] = make_float4(W1g[k0 * 64 + l], W1g[k0 * 64 + l + 32],
                              W1g[(k0 + 1) * 64 + l], W1g[(k0 + 1) * 64 + l + 32]);
    }
    __syncthreads();
    int wid = tid >> 5, lane = tid & 31;
    float b1l = b1g[lane], b1h = b1g[lane + 32];
    float w2l = W2g[lane], w2h = W2g[lane + 32];
    float b2s = b2g[0];
    float* shf = (float*)&s_hq[wid][0][0];
    int nQ = (K + 3) >> 2;
    int q = blockIdx.x * 8 + wid;
    if (q >= nQ) return;
    int c0 = q << 2;
#pragma unroll
    for (int r = 0; r < 4; r++) {
        if (c0 + r < K) {
            int node = idx_at(cand, c0 + r, is64, nN);
            int rk = g_rank[node];
            const float* hr = (rk >= 0) ? g_hpA + (size_t)rk * 64
                                        : g_h + (size_t)node * 64;
            shf[r * 64 + lane] = hr[lane];
            shf[r * 64 + lane + 32] = hr[lane + 32];
        } else {
            shf[r * 64 + lane] = 0.f;
            shf[r * 64 + lane + 32] = 0.f;
        }
    }
    __syncwarp();
    float tl[4], th[4];
#pragma unroll
    for (int r = 0; r < 4; r++) { tl[r] = b1l; th[r] = b1h; }
#pragma unroll
    for (int kq = 0; kq < 16; ++kq) {
        float4 w0 = s_W1[(2 * kq) * 32 + lane];
        float4 w1 = s_W1[(2 * kq + 1) * 32 + lane];
#pragma unroll
        for (int r = 0; r < 4; r++) {
            float4 hv = s_hq[wid][r][kq];
            tl[r] += hv.x * w0.x + hv.y * w0.z + hv.z * w1.x + hv.w * w1.z;
            th[r] += hv.x * w0.y + hv.y * w0.w + hv.z * w1.y + hv.w * w1.w;
        }
    }
#pragma unroll
    for (int r = 0; r < 4; r++) {
        float s = leaky(tl[r]) * w2l + leaky(th[r]) * w2h;
        s = wsum(s) + b2s;
        if (lane == 0 && c0 + r < K) g_scores[c0 + r] = s;
    }
}

__global__ __launch_bounds__(256) void softmax_kernel(float* __restrict__ out, int K) {
    __shared__ float s_red[256];
    int tid = threadIdx.x;
    float m = -3.4e38f;
    for (int i = tid; i < K; i += 256) m = fmaxf(m, g_scores[i]);
    s_red[tid] = m; __syncthreads();
    for (int o = 128; o; o >>= 1) { if (tid < o) s_red[tid] = fmaxf(s_red[tid], s_red[tid + o]); __syncthreads(); }
    m = s_red[0];
    __syncthreads();
    float sum = 0.f;
    for (int i = tid; i < K; i += 256) sum += expf(g_scores[i] - m);
    s_red[tid] = sum; __syncthreads();
    for (int o = 128; o; o >>= 1) { if (tid < o) s_red[tid] += s_red[tid + o]; __syncthreads(); }
    float invT = 1.f / s_red[0];
    for (int i = tid; i < K; i += 256) out[i] = expf(g_scores[i] - m) * invT;
}

// ---------------- launch ----------------
extern "C" void kernel_launch(void* const* d_in, const int* in_sizes, int n_in,
                              void* d_out, int out_size) {
    const float* x     = (const float*)d_in[0];
    const void*  ei    = d_in[1];
    const void*  cand  = d_in[2];
    const float* pW    = (const float*)d_in[3];
    const float* pb    = (const float*)d_in[4];
    const float* eW    = (const float*)d_in[5];
    const float* eb    = (const float*)d_in[6];
    const float* gamma = (const float*)d_in[7];
    const float* beta  = (const float*)d_in[8];
    const float* sW1   = (const float*)d_in[9];
    const float* sb1   = (const float*)d_in[10];
    const float* sW2   = (const float*)d_in[11];
    const float* sb2   = (const float*)d_in[12];
    const float* hW1   = (const float*)d_in[13];
    const float* hb1   = (const float*)d_in[14];
    const float* hW2   = (const float*)d_in[15];
    const float* hb2   = (const float*)d_in[16];

    int nN = in_sizes[0] / FIN;
    int E  = in_sizes[1] / 2;
    int K  = in_sizes[2];

    int nb256 = (nN + 255) / 256;
    int eb256 = (E + 255) / 256;
    int scanBlocks = (nN + 1023) / 1024;

    // launch order: 4th launch (ncu capture slot) is embed_kernel
    detect_kernel<<<1, 256>>>((const unsigned*)ei, E);              // 1
    zero_kernel<<<nb256, 256>>>(nN);                                // 2
    hist_kernel<<<eb256, 256>>>(ei, E, nN);                         // 3
    embed_kernel<<<444, 128>>>(x, pW, pb, eW, eb, gamma, beta, nN); // 4 <- profiled
    scan_cnt_kernel<<<scanBlocks, 256>>>(nN);                       // 5
    scan_bsum_kernel<<<1, 256>>>(scanBlocks);                       // 6
    addback_kernel<<<nb256, 256>>>(nN);                             // 7
    scatter_kernel<<<eb256, 256>>>(ei, E, nN);                      // 8

    // double-buffered fused message passing: A <- iter0, B <- iter1, A <- iter2
    mp_kernel<<<444, 256>>>(sW1,          sb1,       sW2,          sb2,       0, 1);
    mp_kernel<<<444, 256>>>(sW1 + 4096,   sb1 + 64,  sW2 + 4096,   sb2 + 64,  1, 2);
    mp_kernel<<<444, 256>>>(sW1 + 8192,   sb1 + 128, sW2 + 8192,   sb2 + 128, 2, 1);

    int sBlocks = ((K + 3) / 4 + 7) / 8;
    scores_kernel<<<sBlocks, 256>>>(cand, hW1, hb1, hW2, hb2, K, nN);
    softmax_kernel<<<1, 256>>>((float*)d_out, K);
}

// round 9
// speedup vs baseline: 26.4721x; 26.4721x over previous
#include <cuda_runtime.h>
#include <cstdint>

#define NMAX 1000000
#define EMAX 1000000
#define HDIM 64
#define FIN  19
#define LN_EPS 1e-5f
#define LCAP 262144
#define ECAP 524288

// ---------------- device scratch ----------------
__device__ float g_h[(size_t)NMAX * HDIM];     // h0 (embed) for N0 nodes
__device__ float g_hpA[(size_t)NMAX * HDIM];   // h1 / h3
__device__ float g_hpB[(size_t)NMAX * HDIM];   // h2
__device__ int   g_stamp[NMAX];                // 0=unset, -1=claimed, idx+1 = list pos
__device__ int   g_list[LCAP];
__device__ int   g_nlist;
__device__ int   g_nl[4];                      // g_nl[k] = |N_k|, k=0..3
__device__ int   g_eP[3 * ECAP];               // per-iter edge parent list-index
__device__ int   g_eC[3 * ECAP];               // per-iter edge child node
__device__ int   g_ecnt[3];
__device__ int   g_cntlv[3 * LCAP];            // per-iter child counts by list idx
__device__ float g_sum[(size_t)LCAP * HDIM];
__device__ int   g_is64;
__device__ float g_scores[4096];

__device__ __forceinline__ float leaky(float v) { return v > 0.f ? v : 0.01f * v; }

__device__ __forceinline__ float wsum(float v) {
#pragma unroll
    for (int o = 16; o; o >>= 1) v += __shfl_xor_sync(0xffffffffu, v, o);
    return v;
}

// device-side buffer selection
__device__ __forceinline__ float* buf_ptr(int sel) {
    return (sel == 0) ? g_h : (sel == 1) ? g_hpA : g_hpB;
}

// ---------------- packed f32x2 helpers ----------------
__device__ __forceinline__ unsigned long long pack2(float lo, float hi) {
    unsigned long long d;
    asm("mov.b64 %0, {%1, %2};" : "=l"(d) : "r"(__float_as_uint(lo)), "r"(__float_as_uint(hi)));
    return d;
}
__device__ __forceinline__ unsigned long long dup2(float v) {
    unsigned long long d;
    unsigned u = __float_as_uint(v);
    asm("mov.b64 %0, {%1, %1};" : "=l"(d) : "r"(u));
    return d;
}
__device__ __forceinline__ void unpack2(unsigned long long v, float& lo, float& hi) {
    unsigned a, b;
    asm("mov.b64 {%0, %1}, %2;" : "=r"(a), "=r"(b) : "l"(v));
    lo = __uint_as_float(a); hi = __uint_as_float(b);
}
__device__ __forceinline__ void fma2(unsigned long long& a, unsigned long long b, unsigned long long c) {
    asm("fma.rn.f32x2 %0, %1, %2, %0;" : "+l"(a) : "l"(b), "l"(c));
}

__device__ __forceinline__ int idx_at(const void* p, int i, int is64, int n) {
    long long v = is64 ? ((const long long*)p)[i] : (long long)((const int*)p)[i];
    unsigned u = (unsigned)v;
    return (u < (unsigned)n) ? (int)u : 0;
}

// ---------------- dtype detection ----------------
__global__ void detect_kernel(const unsigned* __restrict__ words, int nPairs) {
    __shared__ int flag;
    if (threadIdx.x == 0) flag = 0;
    __syncthreads();
    int lim = nPairs < 256 ? nPairs : 256;
    int i = threadIdx.x;
    if (i < lim && words[2 * i + 1] != 0u) flag = 1;
    __syncthreads();
    if (threadIdx.x == 0) g_is64 = (flag == 0);
}

// ---------------- per-replay reset ----------------
__global__ void reset_kernel() {
    size_t stride = (size_t)gridDim.x * blockDim.x;
    for (size_t i = (size_t)blockIdx.x * blockDim.x + threadIdx.x; i < NMAX; i += stride) {
        g_stamp[i] = 0;
        if (i < 3 * LCAP) g_cntlv[i] = 0;
    }
    if (blockIdx.x == 0 && threadIdx.x == 0) {
        g_nlist = 0;
        g_ecnt[0] = g_ecnt[1] = g_ecnt[2] = 0;
        g_nl[0] = g_nl[1] = g_nl[2] = g_nl[3] = 0;
    }
}

// ---------------- mark candidates (single block) + snapshot n3 ----------------
__global__ void mark_cands_kernel(const void* __restrict__ cand, int K, int nN) {
    int is64 = g_is64;
    for (int i = threadIdx.x; i < K; i += blockDim.x) {
        int node = idx_at(cand, i, is64, nN);
        if (atomicCAS(&g_stamp[node], 0, -1) == 0) {
            int li = atomicAdd(&g_nlist, 1);
            if (li < LCAP) { g_list[li] = node; __threadfence(); g_stamp[node] = li + 1; }
        }
    }
    __syncthreads();
    if (threadIdx.x == 0) {
        int v = g_nlist;
        g_nl[3] = v < LCAP ? v : LCAP;
    }
}

__global__ void snap_kernel(int k) {
    if (threadIdx.x == 0) {
        int v = g_nlist;
        g_nl[k] = v < LCAP ? v : LCAP;
    }
}

// ---- edge pass for iteration k: collect active edges + counts, expand list ----
__global__ void pass_kernel(const void* __restrict__ ei, int E, int nN, int k) {
    int is64 = g_is64;
    int e = blockIdx.x * blockDim.x + threadIdx.x;
    if (e >= E) return;
    int p = idx_at(ei, e, is64, nN);
    int s = g_stamp[p];
    if (s > 0 && s <= g_nl[k]) {
        int c = idx_at(ei, E + e, is64, nN);
        int pi = s - 1;
        atomicAdd(&g_cntlv[(k - 1) * LCAP + pi], 1);
        int ex = atomicAdd(&g_ecnt[k - 1], 1);
        if (ex < ECAP) {
            g_eP[(k - 1) * ECAP + ex] = pi;
            g_eC[(k - 1) * ECAP + ex] = c;
        }
        if (g_stamp[c] == 0) {
            if (atomicCAS(&g_stamp[c], 0, -1) == 0) {
                int li = atomicAdd(&g_nlist, 1);
                if (li < LCAP) { g_list[li] = c; __threadfence(); g_stamp[c] = li + 1; }
            }
        }
    }
}

// ---------------- embedding for list nodes (packed f32x2, 8 nodes/warp) ------
__global__ __launch_bounds__(128) void embed_list_kernel(
    const float* __restrict__ x, const float* __restrict__ pW, const float* __restrict__ pb,
    const float* __restrict__ eW, const float* __restrict__ eb,
    const float* __restrict__ gamma, const float* __restrict__ beta, int nN)
{
    __shared__ float4 s_pW[10 * 32];
    __shared__ float4 s_eW[2 * 32 * 32];
    __shared__ float4 s_x[4][8][5];
    __shared__ float4 s_h[4][8][16];
    int tid = threadIdx.x;
    for (int i = tid; i < 10 * 32; i += 128) {
        int kp = i >> 5, l = i & 31;
        int k0 = 2 * kp, k1 = 2 * kp + 1;
        float a = (k0 < FIN) ? pW[k0 * 64 + l]      : 0.f;
        float b = (k0 < FIN) ? pW[k0 * 64 + l + 32] : 0.f;
        float c = (k1 < FIN) ? pW[k1 * 64 + l]      : 0.f;
        float d = (k1 < FIN) ? pW[k1 * 64 + l + 32] : 0.f;
        s_pW[i] = make_float4(a, b, c, d);
    }
    for (int i = tid; i < 2 * 32 * 32; i += 128) {
        int li = i >> 10, r = i & 1023, kp = r >> 5, l = r & 31;
        const float* W = eW + li * 4096;
        int k0 = 2 * kp;
        s_eW[i] = make_float4(W[k0 * 64 + l], W[k0 * 64 + l + 32],
                              W[(k0 + 1) * 64 + l], W[(k0 + 1) * 64 + l + 32]);
    }
    __syncthreads();

    int wid = tid >> 5, lane = tid & 31;
    unsigned long long pb2 = pack2(pb[lane], pb[lane + 32]);
    unsigned long long eb2[2];
    float gl[2], ghi[2], bl[2], bh[2];
#pragma unroll
    for (int i2 = 0; i2 < 2; i2++) {
        eb2[i2] = pack2(eb[i2 * 64 + lane], eb[i2 * 64 + lane + 32]);
        gl[i2] = gamma[i2 * 64 + lane];  ghi[i2] = gamma[i2 * 64 + lane + 32];
        bl[i2] = beta[i2 * 64 + lane];   bh[i2] = beta[i2 * 64 + lane + 32];
    }
    float* sxf = (float*)&s_x[wid][0][0];
    float* shf = (float*)&s_h[wid][0][0];

    int n0 = g_nl[0];
    int nG = (n0 + 7) >> 3;
    for (int g = blockIdx.x * 4 + wid; g < nG; g += gridDim.x * 4) {
        int i0 = g << 3;
        int nd = (lane < 8 && i0 + lane < n0) ? g_list[i0 + lane] : -1;
        // broadcast the 8 node ids in UNIFORM control flow (R7/R8 bug:
        // __shfl_sync inside the ragged staging loop = UB -> garbage index)
        int ndv[8];
#pragma unroll
        for (int r = 0; r < 8; r++) ndv[r] = __shfl_sync(0xffffffffu, nd, r);
        __syncwarp();
        for (int idx = lane; idx < 8 * FIN; idx += 32) {
            int r = idx / FIN, kk = idx - r * FIN;
            int node = ndv[r];
            sxf[r * 20 + kk] = (node >= 0) ? x[(size_t)node * FIN + kk] : 0.f;
        }
        if (lane < 8) sxf[lane * 20 + 19] = 0.f;
        __syncwarp();

        unsigned long long acc[8];
#pragma unroll
        for (int r = 0; r < 8; r++) acc[r] = pb2;
#pragma unroll
        for (int kq = 0; kq < 5; ++kq) {
            ulonglong2 w0 = *(const ulonglong2*)&s_pW[(2 * kq) * 32 + lane];
            ulonglong2 w1 = *(const ulonglong2*)&s_pW[(2 * kq + 1) * 32 + lane];
#pragma unroll
            for (int r = 0; r < 8; r++) {
                float4 xv = s_x[wid][r][kq];
                fma2(acc[r], w0.x, dup2(xv.x));
                fma2(acc[r], w0.y, dup2(xv.y));
                fma2(acc[r], w1.x, dup2(xv.z));
                fma2(acc[r], w1.y, dup2(xv.w));
            }
        }
        float hl[8], hh[8];
#pragma unroll
        for (int r = 0; r < 8; r++) {
            float a, b; unpack2(acc[r], a, b);
            hl[r] = leaky(a); hh[r] = leaky(b);
        }

#pragma unroll
        for (int li = 0; li < 2; ++li) {
#pragma unroll
            for (int r = 0; r < 8; r++) { shf[r * 64 + lane] = hl[r]; shf[r * 64 + lane + 32] = hh[r]; }
            __syncwarp();
#pragma unroll
            for (int r = 0; r < 8; r++) acc[r] = eb2[li];
#pragma unroll
            for (int kq = 0; kq < 16; ++kq) {
                ulonglong2 w0 = *(const ulonglong2*)&s_eW[li * 1024 + (2 * kq) * 32 + lane];
                ulonglong2 w1 = *(const ulonglong2*)&s_eW[li * 1024 + (2 * kq + 1) * 32 + lane];
#pragma unroll
                for (int r = 0; r < 8; r++) {
                    float4 hv = s_h[wid][r][kq];
                    fma2(acc[r], w0.x, dup2(hv.x));
                    fma2(acc[r], w0.y, dup2(hv.y));
                    fma2(acc[r], w1.x, dup2(hv.z));
                    fma2(acc[r], w1.y, dup2(hv.w));
                }
            }
#pragma unroll
            for (int r = 0; r < 8; r++) {
                float tl, th; unpack2(acc[r], tl, th);
                float ul = hl[r] + leaky(tl);
                float uh = hh[r] + leaky(th);
                float s1 = wsum(ul + uh);
                float s2 = wsum(ul * ul + uh * uh);
                float mu = s1 * (1.f / 64.f);
                float var = s2 * (1.f / 64.f) - mu * mu;
                float inv = rsqrtf(var + LN_EPS);
                hl[r] = (ul - mu) * inv * gl[li] + bl[li];
                hh[r] = (uh - mu) * inv * ghi[li] + bh[li];
            }
            __syncwarp();
        }
#pragma unroll
        for (int r = 0; r < 8; r++) {
            if (ndv[r] >= 0) {
                g_h[(size_t)ndv[r] * 64 + lane] = hl[r];
                g_h[(size_t)ndv[r] * 64 + lane + 32] = hh[r];
            }
        }
    }
}

// ---------------- per-iter sum clear / edge-parallel accumulate ----------------
__global__ void clear_sum_kernel(int k) {
    size_t n = (size_t)g_nl[k] * 64;
    size_t stride = (size_t)gridDim.x * blockDim.x;
    for (size_t i = (size_t)blockIdx.x * blockDim.x + threadIdx.x; i < n; i += stride)
        g_sum[i] = 0.f;
}

__global__ void accum_kernel(int prevSel, int k) {
    const float* prev = buf_ptr(prevSel);
    int lane = threadIdx.x & 31;
    int w = (blockIdx.x * blockDim.x + threadIdx.x) >> 5;
    int nw = (gridDim.x * blockDim.x) >> 5;
    int ne = g_ecnt[k - 1]; if (ne > ECAP) ne = ECAP;
    for (int e = w; e < ne; e += nw) {
        int pi = g_eP[(k - 1) * ECAP + e];
        int c  = g_eC[(k - 1) * ECAP + e];
        const float* hr = prev + (size_t)c * 64;
        atomicAdd(&g_sum[(size_t)pi * 64 + lane], hr[lane]);
        atomicAdd(&g_sum[(size_t)pi * 64 + lane + 32], hr[lane + 32]);
    }
}

// ---------------- node-parallel MP update (mean -> MLP -> residual) ----------
__global__ __launch_bounds__(256) void mpnode_kernel(
    const float* __restrict__ W1g, const float* __restrict__ b1g,
    const float* __restrict__ W2g, const float* __restrict__ b2g,
    int prevSel, int outSel, int k)
{
    __shared__ float4 s_W1[1024];
    __shared__ float4 s_W2[1024];
    __shared__ float4 s_hq[8][4][16];
    int tid = threadIdx.x;
    for (int i = tid; i < 1024; i += 256) {
        int kp = i >> 5, l = i & 31; int k0 = kp * 2;
        s_W1[i] = make_float4(W1g[k0 * 64 + l], W1g[k0 * 64 + l + 32],
                              W1g[(k0 + 1) * 64 + l], W1g[(k0 + 1) * 64 + l + 32]);
        s_W2[i] = make_float4(W2g[k0 * 64 + l], W2g[k0 * 64 + l + 32],
                              W2g[(k0 + 1) * 64 + l], W2g[(k0 + 1) * 64 + l + 32]);
    }
    __syncthreads();
    const float* prev = buf_ptr(prevSel);
    float* out = buf_ptr(outSel);
    int wid = tid >> 5, lane = tid & 31;
    float b1l = b1g[lane], b1h = b1g[lane + 32];
    float b2l = b2g[lane], b2h = b2g[lane + 32];
    float* shf = (float*)&s_hq[wid][0][0];
    int n = g_nl[k];
    int cb = (k - 1) * LCAP;
    for (int i0 = (blockIdx.x * 8 + wid) * 4; i0 < n; i0 += gridDim.x * 32) {
        int nodes[4], ccs[4];
        __syncwarp();
#pragma unroll
        for (int r = 0; r < 4; r++) {
            int ix = i0 + r;
            float ml = 0.f, mh = 0.f;
            if (ix < n) {
                nodes[r] = g_list[ix];
                ccs[r] = g_cntlv[cb + ix];
                if (ccs[r] > 0) {
                    float inv = 1.f / (float)ccs[r];
                    ml = g_sum[(size_t)ix * 64 + lane] * inv;
                    mh = g_sum[(size_t)ix * 64 + lane + 32] * inv;
                }
            } else { nodes[r] = -1; ccs[r] = 0; }
            shf[r * 64 + lane] = ml;
            shf[r * 64 + lane + 32] = mh;
        }
        __syncwarp();
        float tl[4], th[4];
#pragma unroll
        for (int r = 0; r < 4; r++) { tl[r] = b1l; th[r] = b1h; }
#pragma unroll
        for (int kq = 0; kq < 16; ++kq) {
            float4 w0 = s_W1[(2 * kq) * 32 + lane];
            float4 w1 = s_W1[(2 * kq + 1) * 32 + lane];
#pragma unroll
            for (int r = 0; r < 4; r++) {
                float4 hv = s_hq[wid][r][kq];
                tl[r] += hv.x * w0.x + hv.y * w0.z + hv.z * w1.x + hv.w * w1.z;
                th[r] += hv.x * w0.y + hv.y * w0.w + hv.z * w1.y + hv.w * w1.w;
            }
        }
        __syncwarp();
#pragma unroll
        for (int r = 0; r < 4; r++) {
            shf[r * 64 + lane] = leaky(tl[r]);
            shf[r * 64 + lane + 32] = leaky(th[r]);
        }
        __syncwarp();
        float ol[4], oh[4];
#pragma unroll
        for (int r = 0; r < 4; r++) { ol[r] = b2l; oh[r] = b2h; }
#pragma unroll
        for (int kq = 0; kq < 16; ++kq) {
            float4 w0 = s_W2[(2 * kq) * 32 + lane];
            float4 w1 = s_W2[(2 * kq + 1) * 32 + lane];
#pragma unroll
            for (int r = 0; r < 4; r++) {
                float4 hv = s_hq[wid][r][kq];
                ol[r] += hv.x * w0.x + hv.y * w0.z + hv.z * w1.x + hv.w * w1.z;
                oh[r] += hv.x * w0.y + hv.y * w0.w + hv.z * w1.y + hv.w * w1.w;
            }
        }
#pragma unroll
        for (int r = 0; r < 4; r++) {
            if (nodes[r] >= 0) {
                const float* pv = prev + (size_t)nodes[r] * 64;
                float* ov = out + (size_t)nodes[r] * 64;
                float dl = (ccs[r] > 0) ? ol[r] : 0.f;
                float dh = (ccs[r] > 0) ? oh[r] : 0.f;
                ov[lane]      = pv[lane] + dl;
                ov[lane + 32] = pv[lane + 32] + dh;
            }
        }
    }
}

// ---------------- score head (parallel) + softmax ----------------
__global__ __launch_bounds__(256) void scores_kernel(
    const void* __restrict__ cand,
    const float* __restrict__ W1g, const float* __restrict__ b1g,
    const float* __restrict__ W2g, const float* __restrict__ b2g,
    int K, int nN)
{
    __shared__ float4 s_W1[1024];
    __shared__ float4 s_hq[8][4][16];
    int tid = threadIdx.x;
    int is64 = g_is64;
    for (int i = tid; i < 1024; i += 256) {
        int kp = i >> 5, l = i & 31; int k0 = kp * 2;
        s_W1[i] = make_float4(W1g[k0 * 64 + l], W1g[k0 * 64 + l + 32],
                              W1g[(k0 + 1) * 64 + l], W1g[(k0 + 1) * 64 + l + 32]);
    }
    __syncthreads();
    int wid = tid >> 5, lane = tid & 31;
    float b1l = b1g[lane], b1h = b1g[lane + 32];
    float w2l = W2g[lane], w2h = W2g[lane + 32];
    float b2s = b2g[0];
    float* shf = (float*)&s_hq[wid][0][0];
    int nQ = (K + 3) >> 2;
    int q = blockIdx.x * 8 + wid;
    if (q >= nQ) return;
    int c0 = q << 2;
#pragma unroll
    for (int r = 0; r < 4; r++) {
        if (c0 + r < K) {
            int node = idx_at(cand, c0 + r, is64, nN);
            const float* hr = g_hpA + (size_t)node * 64;   // h3 lives in A
            shf[r * 64 + lane] = hr[lane];
            shf[r * 64 + lane + 32] = hr[lane + 32];
        } else {
            shf[r * 64 + lane] = 0.f;
            shf[r * 64 + lane + 32] = 0.f;
        }
    }
    __syncwarp();
    float tl[4], th[4];
#pragma unroll
    for (int r = 0; r < 4; r++) { tl[r] = b1l; th[r] = b1h; }
#pragma unroll
    for (int kq = 0; kq < 16; ++kq) {
        float4 w0 = s_W1[(2 * kq) * 32 + lane];
        float4 w1 = s_W1[(2 * kq + 1) * 32 + lane];
#pragma unroll
        for (int r = 0; r < 4; r++) {
            float4 hv = s_hq[wid][r][kq];
            tl[r] += hv.x * w0.x + hv.y * w0.z + hv.z * w1.x + hv.w * w1.z;
            th[r] += hv.x * w0.y + hv.y * w0.w + hv.z * w1.y + hv.w * w1.w;
        }
    }
#pragma unroll
    for (int r = 0; r < 4; r++) {
        float s = leaky(tl[r]) * w2l + leaky(th[r]) * w2h;
        s = wsum(s) + b2s;
        if (lane == 0 && c0 + r < K) g_scores[c0 + r] = s;
    }
}

__global__ __launch_bounds__(256) void softmax_kernel(float* __restrict__ out, int K) {
    __shared__ float s_red[256];
    int tid = threadIdx.x;
    float m = -3.4e38f;
    for (int i = tid; i < K; i += 256) m = fmaxf(m, g_scores[i]);
    s_red[tid] = m; __syncthreads();
    for (int o = 128; o; o >>= 1) { if (tid < o) s_red[tid] = fmaxf(s_red[tid], s_red[tid + o]); __syncthreads(); }
    m = s_red[0];
    __syncthreads();
    float sum = 0.f;
    for (int i = tid; i < K; i += 256) sum += expf(g_scores[i] - m);
    s_red[tid] = sum; __syncthreads();
    for (int o = 128; o; o >>= 1) { if (tid < o) s_red[tid] += s_red[tid + o]; __syncthreads(); }
    float invT = 1.f / s_red[0];
    for (int i = tid; i < K; i += 256) out[i] = expf(g_scores[i] - m) * invT;
}

// ---------------- launch ----------------
extern "C" void kernel_launch(void* const* d_in, const int* in_sizes, int n_in,
                              void* d_out, int out_size) {
    const float* x     = (const float*)d_in[0];
    const void*  ei    = d_in[1];
    const void*  cand  = d_in[2];
    const float* pW    = (const float*)d_in[3];
    const float* pb    = (const float*)d_in[4];
    const float* eW    = (const float*)d_in[5];
    const float* eb    = (const float*)d_in[6];
    const float* gamma = (const float*)d_in[7];
    const float* beta  = (const float*)d_in[8];
    const float* sW1   = (const float*)d_in[9];
    const float* sb1   = (const float*)d_in[10];
    const float* sW2   = (const float*)d_in[11];
    const float* sb2   = (const float*)d_in[12];
    const float* hW1   = (const float*)d_in[13];
    const float* hb1   = (const float*)d_in[14];
    const float* hW2   = (const float*)d_in[15];
    const float* hb2   = (const float*)d_in[16];

    int nN = in_sizes[0] / FIN;
    int E  = in_sizes[1] / 2;
    int K  = in_sizes[2];
    int eb256 = (E + 255) / 256;

    detect_kernel<<<1, 256>>>((const unsigned*)ei, E);              // 1
    reset_kernel<<<2048, 256>>>();                                  // 2
    mark_cands_kernel<<<1, 512>>>(cand, K, nN);                     // 3 (sets n3)
    pass_kernel<<<eb256, 256>>>(ei, E, nN, 3);                      // 4 <- profiled
    snap_kernel<<<1, 32>>>(2);                                      // 5
    pass_kernel<<<eb256, 256>>>(ei, E, nN, 2);                      // 6
    snap_kernel<<<1, 32>>>(1);                                      // 7
    pass_kernel<<<eb256, 256>>>(ei, E, nN, 1);                      // 8
    snap_kernel<<<1, 32>>>(0);                                      // 9

    embed_list_kernel<<<128, 128>>>(x, pW, pb, eW, eb, gamma, beta, nN);

    // iter 1: g_h(0) -> A(1) ; iter 2: A(1) -> B(2) ; iter 3: B(2) -> A(1)
    const int prevSel[3] = { 0, 1, 2 };
    const int outSel[3]  = { 1, 2, 1 };
    for (int it = 0; it < 3; ++it) {
        int k = it + 1;
        clear_sum_kernel<<<64, 256>>>(k);
        accum_kernel<<<64, 256>>>(prevSel[it], k);
        mpnode_kernel<<<64, 256>>>(sW1 + it * 4096, sb1 + it * 64,
                                   sW2 + it * 4096, sb2 + it * 64,
                                   prevSel[it], outSel[it], k);
    }

    int sBlocks = ((K + 3) / 4 + 7) / 8;
    scores_kernel<<<sBlocks, 256>>>(cand, hW1, hb1, hW2, hb2, K, nN);
    softmax_kernel<<<1, 256>>>((float*)d_out, K);
}